// round 16
// baseline (speedup 1.0000x reference)
#include <cuda_runtime.h>
#include <cstdint>

// NativeSparseAttention: S=8192, B=16, E=128, fp32
// Persistent kernel, warp-level tf32 mma.sync (m16n8k8), 512 threads, 1 CTA/SM.
// R15 = R14 + (1) non-volatile mma asm -> ptxas can software-pipeline the
// fused loop; (2) inv via intra-warp shuffles (no smem round-trip);
// (3) x double-buffered per half -> barrier (C) eliminated (2 bars/iter).

#define S_TOTAL 8192

// strides (floats)
#define SW 132    // W: bank 4*qr+qc          -> conflict-free
#define SX 132    // x: bank 4*sigma(qr)+qc   -> conflict-free
#define SV 136    // v: bank 8*qc+sigma(qr)   -> conflict-free

// smem offsets (floats)
#define OFF_WK  0
#define OFF_WV  (128 * SW)                 // 16896
#define OFF_X   (OFF_WV + 128 * SW)        // 33792 ; 2 halves x 2 bufs x 16 x SX
#define OFF_V   (OFF_X + 4 * 16 * SX)      // 42240 ; 2 halves x 16 x SV
#define SMEM_FLOATS (OFF_V + 2 * 16 * SV)  // 46592
#define SMEM_BYTES  (SMEM_FLOATS * 4)      // 186368

__device__ __forceinline__ uint32_t f2t(float f) {
    uint32_t u; asm("cvt.rna.tf32.f32 %0, %1;" : "=r"(u) : "f"(f)); return u;
}
__device__ __forceinline__ float ex2f(float x) {
    float y; asm("ex2.approx.f32 %0, %1;" : "=f"(y) : "f"(x)); return y;
}
// NOTE: not volatile — pure register op; lets ptxas pipeline MMAs with loads.
__device__ __forceinline__ void mma8(float* d, const uint32_t* a, const uint32_t* b) {
    asm("mma.sync.aligned.m16n8k8.row.col.f32.tf32.tf32.f32 "
        "{%0,%1,%2,%3}, {%4,%5,%6,%7}, {%8,%9}, {%0,%1,%2,%3};"
        : "+f"(d[0]), "+f"(d[1]), "+f"(d[2]), "+f"(d[3])
        : "r"(a[0]), "r"(a[1]), "r"(a[2]), "r"(a[3]), "r"(b[0]), "r"(b[1]));
}

__global__ __launch_bounds__(512, 1)
void nsa_mma(const float* __restrict__ x,
             const float* __restrict__ Wk,
             const float* __restrict__ bk,
             const float* __restrict__ Wv,
             const float* __restrict__ bv,
             float* __restrict__ out) {
    extern __shared__ float sm[];
    uint32_t* smu = reinterpret_cast<uint32_t*>(sm);

    const int t = threadIdx.x;
    const int half = t >> 8;                    // 0 or 1: which s this thread works
    const int tl = t & 255;                     // thread id within half
    const int lid = t & 31;
    const int qr = lid >> 2;                    // groupID 0..7
    const int qc = lid & 3;                     // threadID-in-group 0..3
    const int sq = (qr >> 1) + 4 * (qr & 1);    // sigma(qr)
    const int ebk = ((tl >> 5)) * 16;           // warp's e-block base (within half)
    const int barid = 1 + half;                 // per-half named barrier
    const unsigned FULL = 0xffffffffu;

    // per-half buffer bases (x double-buffered)
    const int xb0 = OFF_X + (half * 2) * (16 * SX);
    const int xb1 = xb0 + (16 * SX);
    const int vb  = OFF_V + half * (16 * SV);

    // ---- one-time: stage Wk/Wv as tf32, row-major stride SW (512 threads) ----
    #pragma unroll
    for (int i = 0; i < 8; i++) {
        const int l = t + 512 * i;          // float4 index over 128x128
        const int r = l >> 5, c = (l & 31) * 4;
        float4 a = reinterpret_cast<const float4*>(Wk)[l];
        uint4 pa = { f2t(a.x), f2t(a.y), f2t(a.z), f2t(a.w) };
        *reinterpret_cast<uint4*>(&smu[OFF_WK + r * SW + c]) = pa;
        float4 b = reinterpret_cast<const float4*>(Wv)[l];
        uint4 pb = { f2t(b.x), f2t(b.y), f2t(b.z), f2t(b.w) };
        *reinterpret_cast<uint4*>(&smu[OFF_WV + r * SW + c]) = pb;
    }
    const float bk0 = __ldg(bk + ebk + qr), bk1 = __ldg(bk + ebk + qr + 8);
    const float bv0 = __ldg(bv + ebk + qr), bv1 = __ldg(bv + ebk + qr + 8);
    const float C2 = 0.015939678942f;       // log2(e)/sqrt(8192)

    const int step = 2 * (int)gridDim.x;
    int s0 = blockIdx.x;                        // half-0's s (loop control)
    int s  = s0 + half * (int)gridDim.x;        // this half's s
    int pb = 0;                                 // x buffer parity
    float4 xr0, xr1;
    if (s < S_TOTAL) {
        const float4* xg = reinterpret_cast<const float4*>(x + (size_t)s * 2048);
        xr0 = xg[tl]; xr1 = xg[tl + 256];
    }
    __syncthreads();   // W visible to all; last full-CTA barrier

    while (s0 < S_TOTAL) {
        const int xb = pb ? xb1 : xb0;

        // ---- stage x (tf32) into this half's current buffer ----
        {
            const int b0i = tl >> 5,         c0 = (tl & 31) * 4;
            const int b1i = (tl + 256) >> 5, c1 = ((tl + 256) & 31) * 4;
            uint4 h;
            h.x = f2t(xr0.x); h.y = f2t(xr0.y); h.z = f2t(xr0.z); h.w = f2t(xr0.w);
            *reinterpret_cast<uint4*>(&smu[xb + b0i * SX + c0]) = h;
            h.x = f2t(xr1.x); h.y = f2t(xr1.y); h.z = f2t(xr1.z); h.w = f2t(xr1.w);
            *reinterpret_cast<uint4*>(&smu[xb + b1i * SX + c1]) = h;
        }
        asm volatile("bar.sync %0, 256;" :: "r"(barid) : "memory");   // (A)

        // ---- prefetch next x into regs ----
        const int snext = s + step;
        if (snext < S_TOTAL) {
            const float4* xg = reinterpret_cast<const float4*>(x + (size_t)snext * 2048);
            xr0 = xg[tl]; xr1 = xg[tl + 256];
        }

        // ======== phase 1: kT = Wk@xT, vT = Wv@xT (M=e16, N=b16 sigma-mapped) ====
        uint32_t xf[8][4];
        float kD[2][4] = {{0,0,0,0},{0,0,0,0}};
        float vD[2][4] = {{0,0,0,0},{0,0,0,0}};
        #pragma unroll
        for (int kk = 0; kk < 16; kk++) {
            const int jb = kk * 8;
            uint32_t aK[4], aV[4], xt[4];
            aK[0] = smu[OFF_WK + (ebk + qr) * SW + jb + qc];
            aK[1] = smu[OFF_WK + (ebk + qr + 8) * SW + jb + qc];
            aK[2] = smu[OFF_WK + (ebk + qr) * SW + jb + qc + 4];
            aK[3] = smu[OFF_WK + (ebk + qr + 8) * SW + jb + qc + 4];
            aV[0] = smu[OFF_WV + (ebk + qr) * SW + jb + qc];
            aV[1] = smu[OFF_WV + (ebk + qr + 8) * SW + jb + qc];
            aV[2] = smu[OFF_WV + (ebk + qr) * SW + jb + qc + 4];
            aV[3] = smu[OFF_WV + (ebk + qr + 8) * SW + jb + qc + 4];
            xt[0] = smu[xb + sq * SX + jb + qc];
            xt[1] = smu[xb + sq * SX + jb + qc + 4];
            xt[2] = smu[xb + (sq + 8) * SX + jb + qc];
            xt[3] = smu[xb + (sq + 8) * SX + jb + qc + 4];
            if (kk < 8) {
                xf[kk][0] = xt[0]; xf[kk][1] = xt[1];
                xf[kk][2] = xt[2]; xf[kk][3] = xt[3];
            }
            mma8(kD[0], aK, &xt[0]); mma8(kD[1], aK, &xt[2]);
            mma8(vD[0], aV, &xt[0]); mma8(vD[1], aV, &xt[2]);
        }

        // k: straight into P2 A-fragments (raw fp32 bits; HW truncates to tf32)
        uint32_t ka0[4], ka1[4];
        ka0[0] = __float_as_uint(kD[0][0] + bk0); ka0[1] = __float_as_uint(kD[0][2] + bk1);
        ka0[2] = __float_as_uint(kD[0][1] + bk0); ka0[3] = __float_as_uint(kD[0][3] + bk1);
        ka1[0] = __float_as_uint(kD[1][0] + bk0); ka1[1] = __float_as_uint(kD[1][2] + bk1);
        ka1[2] = __float_as_uint(kD[1][1] + bk0); ka1[3] = __float_as_uint(kD[1][3] + bk1);

        // v -> smem [b][f], b-cols sigma-mapped
        #pragma unroll
        for (int nt = 0; nt < 2; nt++) {
            const int b0c = nt * 8 + qc;
            smu[vb + b0c * SV + ebk + qr]           = f2t(vD[nt][0] + bv0);
            smu[vb + (b0c + 4) * SV + ebk + qr]     = f2t(vD[nt][1] + bv0);
            smu[vb + b0c * SV + ebk + qr + 8]       = f2t(vD[nt][2] + bv1);
            smu[vb + (b0c + 4) * SV + ebk + qr + 8] = f2t(vD[nt][3] + bv1);
        }
        asm volatile("bar.sync %0, 256;" :: "r"(barid) : "memory");   // (B)

        // ======== fused phase 2+3 per f-tile: scores->exp->O accumulate ========
        float Oe[2][4] = {{0,0,0,0},{0,0,0,0}};
        float Oo[2][4] = {{0,0,0,0},{0,0,0,0}};
        float s0sum = 0.0f, s1sum = 0.0f;
        #pragma unroll
        for (int nt = 0; nt < 16; nt++) {
            float S4[4] = {0, 0, 0, 0};
            uint32_t b[2];
            b[0] = smu[vb + qc * SV + nt * 8 + sq];
            b[1] = smu[vb + (qc + 4) * SV + nt * 8 + sq];
            mma8(S4, ka0, b);
            b[0] = smu[vb + (8 + qc) * SV + nt * 8 + sq];
            b[1] = smu[vb + (8 + qc + 4) * SV + nt * 8 + sq];
            mma8(S4, ka1, b);
            const float e0 = ex2f(S4[0] * C2), e1 = ex2f(S4[1] * C2);
            const float e2 = ex2f(S4[2] * C2), e3 = ex2f(S4[3] * C2);
            s0sum += e0 + e1;
            s1sum += e2 + e3;
            uint32_t bf0[2] = { __float_as_uint(e0), __float_as_uint(e1) };
            uint32_t bf1[2] = { __float_as_uint(e2), __float_as_uint(e3) };
            uint32_t a[4];
            if (nt < 8) {
                a[0] = xf[nt][0]; a[1] = xf[nt][2]; a[2] = xf[nt][1]; a[3] = xf[nt][3];
            } else {
                const int fb = nt * 8;
                a[0] = smu[xb + sq * SX + fb + qc];
                a[1] = smu[xb + (sq + 8) * SX + fb + qc];
                a[2] = smu[xb + sq * SX + fb + qc + 4];
                a[3] = smu[xb + (sq + 8) * SX + fb + qc + 4];
            }
            float* O0 = (nt & 1) ? Oo[0] : Oe[0];
            float* O1 = (nt & 1) ? Oo[1] : Oe[1];
            mma8(O0, a, bf0);
            mma8(O1, a, bf1);
        }

        // row sums over qc group (all 4 lanes of each qr-group get full sum)
        s0sum += __shfl_xor_sync(FULL, s0sum, 1);
        s0sum += __shfl_xor_sync(FULL, s0sum, 2);
        s1sum += __shfl_xor_sync(FULL, s1sum, 1);
        s1sum += __shfl_xor_sync(FULL, s1sum, 2);

        // inv via intra-warp shuffles: e-rows are warp-local.
        // nt2=0 cols: e_local = 2qc, 2qc+1 -> s0sum from lanes 8qc, 8qc+4
        // nt2=1 cols: e_local = 8+2qc, .. -> s1sum from lanes 8qc, 8qc+4
        const float ia0 = 1.0f / __shfl_sync(FULL, s0sum, 8 * qc);
        const float ib0 = 1.0f / __shfl_sync(FULL, s0sum, 8 * qc + 4);
        const float ia1 = 1.0f / __shfl_sync(FULL, s1sum, 8 * qc);
        const float ib1 = 1.0f / __shfl_sync(FULL, s1sum, 8 * qc + 4);

        // ======== epilogue: out[b=sigma(qr)(+8)][e] = O * inv[e] ========
        if (s < S_TOTAL) {
            float* op = out + (size_t)s * 2048;
            {
                const int ec = ebk + 2 * qc;
                const float o0 = Oe[0][0] + Oo[0][0];
                const float o1 = Oe[0][1] + Oo[0][1];
                const float o2 = Oe[0][2] + Oo[0][2];
                const float o3 = Oe[0][3] + Oo[0][3];
                *reinterpret_cast<float2*>(&op[sq * 128 + ec]) =
                    make_float2(o0 * ia0, o1 * ib0);
                *reinterpret_cast<float2*>(&op[(sq + 8) * 128 + ec]) =
                    make_float2(o2 * ia0, o3 * ib0);
            }
            {
                const int ec = ebk + 8 + 2 * qc;
                const float o0 = Oe[1][0] + Oo[1][0];
                const float o1 = Oe[1][1] + Oo[1][1];
                const float o2 = Oe[1][2] + Oo[1][2];
                const float o3 = Oe[1][3] + Oo[1][3];
                *reinterpret_cast<float2*>(&op[sq * 128 + ec]) =
                    make_float2(o0 * ia1, o1 * ib1);
                *reinterpret_cast<float2*>(&op[(sq + 8) * 128 + ec]) =
                    make_float2(o2 * ia1, o3 * ib1);
            }
        }
        s0 += step; s += step; pb ^= 1;
    }
}

extern "C" void kernel_launch(void* const* d_in, const int* in_sizes, int n_in,
                              void* d_out, int out_size) {
    const float* x  = (const float*)d_in[0];
    const float* Wk = (const float*)d_in[1];
    const float* bk = (const float*)d_in[2];
    const float* Wv = (const float*)d_in[3];
    const float* bv = (const float*)d_in[4];
    float* out = (float*)d_out;

    int sms = 148;
    cudaDeviceGetAttribute(&sms, cudaDevAttrMultiProcessorCount, 0);
    if (sms <= 0) sms = 148;
    cudaFuncSetAttribute(nsa_mma, cudaFuncAttributeMaxDynamicSharedMemorySize, SMEM_BYTES);
    nsa_mma<<<sms, 512, SMEM_BYTES>>>(x, Wk, bk, Wv, bv, out);
}

// round 17
// speedup vs baseline: 1.0427x; 1.0427x over previous
#include <cuda_runtime.h>
#include <cstdint>

// NativeSparseAttention: S=8192, B=16, E=128, fp32
// Persistent kernel, warp-level tf32 mma.sync (m16n8k8), 512 threads, 1 CTA/SM.
// R16: 4 s per CTA-iteration. Each 256-thread pair handles an s-pair; P1
// computes k/v for BOTH s per W-fragment load (halves per-s W LDS traffic).
// Fused P2+3 runs sequentially per s. 1.5 barriers/s (was 2).

#define S_TOTAL 8192

// strides (floats)
#define SW 132    // W: bank 4*qr+qc          -> conflict-free
#define SX 132    // x: bank 4*sigma(qr)+qc   -> conflict-free
#define SV 136    // v: bank 8*qc+sigma(qr)   -> conflict-free

// smem offsets (floats)
#define OFF_WK  0
#define OFF_WV  (128 * SW)                 // 16896
#define OFF_X   (OFF_WV + 128 * SW)        // 33792 ; 4 bufs x 16 x SX
#define OFF_V   (OFF_X + 4 * 16 * SX)      // 42240 ; 4 bufs x 16 x SV
#define SMEM_FLOATS (OFF_V + 4 * 16 * SV)  // 50944
#define SMEM_BYTES  (SMEM_FLOATS * 4)      // 203776

__device__ __forceinline__ uint32_t f2t(float f) {
    uint32_t u; asm("cvt.rna.tf32.f32 %0, %1;" : "=r"(u) : "f"(f)); return u;
}
__device__ __forceinline__ float ex2f(float x) {
    float y; asm("ex2.approx.f32 %0, %1;" : "=f"(y) : "f"(x)); return y;
}
__device__ __forceinline__ void mma8(float* d, const uint32_t* a, const uint32_t* b) {
    asm("mma.sync.aligned.m16n8k8.row.col.f32.tf32.tf32.f32 "
        "{%0,%1,%2,%3}, {%4,%5,%6,%7}, {%8,%9}, {%0,%1,%2,%3};"
        : "+f"(d[0]), "+f"(d[1]), "+f"(d[2]), "+f"(d[3])
        : "r"(a[0]), "r"(a[1]), "r"(a[2]), "r"(a[3]), "r"(b[0]), "r"(b[1]));
}

__global__ __launch_bounds__(512, 1)
void nsa_mma(const float* __restrict__ x,
             const float* __restrict__ Wk,
             const float* __restrict__ bk,
             const float* __restrict__ Wv,
             const float* __restrict__ bv,
             float* __restrict__ out) {
    extern __shared__ float sm[];
    uint32_t* smu = reinterpret_cast<uint32_t*>(sm);

    const int t = threadIdx.x;
    const int p = t >> 8;                       // pair id: 0 or 1
    const int tl = t & 255;                     // thread id within pair
    const int lid = t & 31;
    const int qr = lid >> 2;                    // groupID 0..7
    const int qc = lid & 3;                     // threadID-in-group 0..3
    const int sq = (qr >> 1) + 4 * (qr & 1);    // sigma(qr)
    const int ebk = ((tl >> 5)) * 16;           // warp's e-block base (within pair)
    const int barid = 1 + p;                    // per-pair named barrier
    const unsigned FULL = 0xffffffffu;

    // per-pair buffers: slot 0 = s_a, slot 1 = s_b
    const int xbA = OFF_X + (p * 2 + 0) * (16 * SX);
    const int xbB = OFF_X + (p * 2 + 1) * (16 * SX);
    const int vbA = OFF_V + (p * 2 + 0) * (16 * SV);
    const int vbB = OFF_V + (p * 2 + 1) * (16 * SV);

    // ---- one-time: stage Wk/Wv as tf32, row-major stride SW (512 threads) ----
    #pragma unroll
    for (int i = 0; i < 8; i++) {
        const int l = t + 512 * i;          // float4 index over 128x128
        const int r = l >> 5, c = (l & 31) * 4;
        float4 a = reinterpret_cast<const float4*>(Wk)[l];
        uint4 pa = { f2t(a.x), f2t(a.y), f2t(a.z), f2t(a.w) };
        *reinterpret_cast<uint4*>(&smu[OFF_WK + r * SW + c]) = pa;
        float4 b = reinterpret_cast<const float4*>(Wv)[l];
        uint4 pb = { f2t(b.x), f2t(b.y), f2t(b.z), f2t(b.w) };
        *reinterpret_cast<uint4*>(&smu[OFF_WV + r * SW + c]) = pb;
    }
    const float bk0 = __ldg(bk + ebk + qr), bk1 = __ldg(bk + ebk + qr + 8);
    const float bv0 = __ldg(bv + ebk + qr), bv1 = __ldg(bv + ebk + qr + 8);
    const float C2 = 0.015939678942f;       // log2(e)/sqrt(8192)

    const int step = 4 * (int)gridDim.x;
    int sbase = (int)blockIdx.x * 4;
    int sA = sbase + 2 * p;
    int sB = sA + 1;
    float4 xrA0, xrA1, xrB0, xrB1;
    {
        const float4* xg = reinterpret_cast<const float4*>(x + (size_t)sA * 2048);
        xrA0 = xg[tl]; xrA1 = xg[tl + 256];
        const float4* yg = reinterpret_cast<const float4*>(x + (size_t)sB * 2048);
        xrB0 = yg[tl]; xrB1 = yg[tl + 256];
    }
    __syncthreads();   // W visible to all; last full-CTA barrier

    while (sbase < S_TOTAL) {
        // ---- stage x for both s (tf32), [b][j] stride SX ----
        {
            const int b0i = tl >> 5,         c0 = (tl & 31) * 4;
            const int b1i = (tl + 256) >> 5, c1 = ((tl + 256) & 31) * 4;
            uint4 h;
            h.x = f2t(xrA0.x); h.y = f2t(xrA0.y); h.z = f2t(xrA0.z); h.w = f2t(xrA0.w);
            *reinterpret_cast<uint4*>(&smu[xbA + b0i * SX + c0]) = h;
            h.x = f2t(xrA1.x); h.y = f2t(xrA1.y); h.z = f2t(xrA1.z); h.w = f2t(xrA1.w);
            *reinterpret_cast<uint4*>(&smu[xbA + b1i * SX + c1]) = h;
            h.x = f2t(xrB0.x); h.y = f2t(xrB0.y); h.z = f2t(xrB0.z); h.w = f2t(xrB0.w);
            *reinterpret_cast<uint4*>(&smu[xbB + b0i * SX + c0]) = h;
            h.x = f2t(xrB1.x); h.y = f2t(xrB1.y); h.z = f2t(xrB1.z); h.w = f2t(xrB1.w);
            *reinterpret_cast<uint4*>(&smu[xbB + b1i * SX + c1]) = h;
        }
        asm volatile("bar.sync %0, 256;" :: "r"(barid) : "memory");   // (A)

        // ---- prefetch next x for both s ----
        {
            const int snA = sA + step, snB = sB + step;
            if (snA < S_TOTAL) {
                const float4* xg = reinterpret_cast<const float4*>(x + (size_t)snA * 2048);
                xrA0 = xg[tl]; xrA1 = xg[tl + 256];
            }
            if (snB < S_TOTAL) {
                const float4* yg = reinterpret_cast<const float4*>(x + (size_t)snB * 2048);
                xrB0 = yg[tl]; xrB1 = yg[tl + 256];
            }
        }

        // ======== phase 1 (both s): kT = Wk@xT, vT = Wv@xT, shared W loads =======
        float kDA[2][4] = {{0,0,0,0},{0,0,0,0}};
        float vDA[2][4] = {{0,0,0,0},{0,0,0,0}};
        float kDB[2][4] = {{0,0,0,0},{0,0,0,0}};
        float vDB[2][4] = {{0,0,0,0},{0,0,0,0}};
        #pragma unroll
        for (int kk = 0; kk < 16; kk++) {
            const int jb = kk * 8;
            uint32_t aK[4], aV[4], xtA[4], xtB[4];
            aK[0] = smu[OFF_WK + (ebk + qr) * SW + jb + qc];
            aK[1] = smu[OFF_WK + (ebk + qr + 8) * SW + jb + qc];
            aK[2] = smu[OFF_WK + (ebk + qr) * SW + jb + qc + 4];
            aK[3] = smu[OFF_WK + (ebk + qr + 8) * SW + jb + qc + 4];
            aV[0] = smu[OFF_WV + (ebk + qr) * SW + jb + qc];
            aV[1] = smu[OFF_WV + (ebk + qr + 8) * SW + jb + qc];
            aV[2] = smu[OFF_WV + (ebk + qr) * SW + jb + qc + 4];
            aV[3] = smu[OFF_WV + (ebk + qr + 8) * SW + jb + qc + 4];
            xtA[0] = smu[xbA + sq * SX + jb + qc];
            xtA[1] = smu[xbA + sq * SX + jb + qc + 4];
            xtA[2] = smu[xbA + (sq + 8) * SX + jb + qc];
            xtA[3] = smu[xbA + (sq + 8) * SX + jb + qc + 4];
            xtB[0] = smu[xbB + sq * SX + jb + qc];
            xtB[1] = smu[xbB + sq * SX + jb + qc + 4];
            xtB[2] = smu[xbB + (sq + 8) * SX + jb + qc];
            xtB[3] = smu[xbB + (sq + 8) * SX + jb + qc + 4];
            mma8(kDA[0], aK, &xtA[0]); mma8(kDA[1], aK, &xtA[2]);
            mma8(vDA[0], aV, &xtA[0]); mma8(vDA[1], aV, &xtA[2]);
            mma8(kDB[0], aK, &xtB[0]); mma8(kDB[1], aK, &xtB[2]);
            mma8(vDB[0], aV, &xtB[0]); mma8(vDB[1], aV, &xtB[2]);
        }

        // k -> P2 A-fragments (raw fp32 bits; HW truncates to tf32)
        uint32_t kaA[2][4], kaB[2][4];
        kaA[0][0] = __float_as_uint(kDA[0][0] + bk0); kaA[0][1] = __float_as_uint(kDA[0][2] + bk1);
        kaA[0][2] = __float_as_uint(kDA[0][1] + bk0); kaA[0][3] = __float_as_uint(kDA[0][3] + bk1);
        kaA[1][0] = __float_as_uint(kDA[1][0] + bk0); kaA[1][1] = __float_as_uint(kDA[1][2] + bk1);
        kaA[1][2] = __float_as_uint(kDA[1][1] + bk0); kaA[1][3] = __float_as_uint(kDA[1][3] + bk1);
        kaB[0][0] = __float_as_uint(kDB[0][0] + bk0); kaB[0][1] = __float_as_uint(kDB[0][2] + bk1);
        kaB[0][2] = __float_as_uint(kDB[0][1] + bk0); kaB[0][3] = __float_as_uint(kDB[0][3] + bk1);
        kaB[1][0] = __float_as_uint(kDB[1][0] + bk0); kaB[1][1] = __float_as_uint(kDB[1][2] + bk1);
        kaB[1][2] = __float_as_uint(kDB[1][1] + bk0); kaB[1][3] = __float_as_uint(kDB[1][3] + bk1);

        // v -> smem [b][f], b-cols sigma-mapped, both s
        #pragma unroll
        for (int nt = 0; nt < 2; nt++) {
            const int b0c = nt * 8 + qc;
            smu[vbA + b0c * SV + ebk + qr]           = f2t(vDA[nt][0] + bv0);
            smu[vbA + (b0c + 4) * SV + ebk + qr]     = f2t(vDA[nt][1] + bv0);
            smu[vbA + b0c * SV + ebk + qr + 8]       = f2t(vDA[nt][2] + bv1);
            smu[vbA + (b0c + 4) * SV + ebk + qr + 8] = f2t(vDA[nt][3] + bv1);
            smu[vbB + b0c * SV + ebk + qr]           = f2t(vDB[nt][0] + bv0);
            smu[vbB + (b0c + 4) * SV + ebk + qr]     = f2t(vDB[nt][1] + bv0);
            smu[vbB + b0c * SV + ebk + qr + 8]       = f2t(vDB[nt][2] + bv1);
            smu[vbB + (b0c + 4) * SV + ebk + qr + 8] = f2t(vDB[nt][3] + bv1);
        }
        asm volatile("bar.sync %0, 256;" :: "r"(barid) : "memory");   // (B)

        // ======== fused phase 2+3, sequentially per s ========
        auto fused = [&](int xb, int vb, const uint32_t (*ka)[4], int s) {
            float Oe[2][4] = {{0,0,0,0},{0,0,0,0}};
            float Oo[2][4] = {{0,0,0,0},{0,0,0,0}};
            float s0sum = 0.0f, s1sum = 0.0f;
            #pragma unroll
            for (int nt = 0; nt < 16; nt++) {
                float S4[4] = {0, 0, 0, 0};
                uint32_t b[2];
                b[0] = smu[vb + qc * SV + nt * 8 + sq];
                b[1] = smu[vb + (qc + 4) * SV + nt * 8 + sq];
                mma8(S4, ka[0], b);
                b[0] = smu[vb + (8 + qc) * SV + nt * 8 + sq];
                b[1] = smu[vb + (8 + qc + 4) * SV + nt * 8 + sq];
                mma8(S4, ka[1], b);
                const float e0 = ex2f(S4[0] * C2), e1 = ex2f(S4[1] * C2);
                const float e2 = ex2f(S4[2] * C2), e3 = ex2f(S4[3] * C2);
                s0sum += e0 + e1;
                s1sum += e2 + e3;
                uint32_t bf0[2] = { __float_as_uint(e0), __float_as_uint(e1) };
                uint32_t bf1[2] = { __float_as_uint(e2), __float_as_uint(e3) };
                const int fb = nt * 8;
                uint32_t a[4];
                a[0] = smu[xb + sq * SX + fb + qc];
                a[1] = smu[xb + (sq + 8) * SX + fb + qc];
                a[2] = smu[xb + sq * SX + fb + qc + 4];
                a[3] = smu[xb + (sq + 8) * SX + fb + qc + 4];
                float* O0 = (nt & 1) ? Oo[0] : Oe[0];
                float* O1 = (nt & 1) ? Oo[1] : Oe[1];
                mma8(O0, a, bf0);
                mma8(O1, a, bf1);
            }
            // row sums over qc group
            s0sum += __shfl_xor_sync(FULL, s0sum, 1);
            s0sum += __shfl_xor_sync(FULL, s0sum, 2);
            s1sum += __shfl_xor_sync(FULL, s1sum, 1);
            s1sum += __shfl_xor_sync(FULL, s1sum, 2);
            const float ia0 = 1.0f / __shfl_sync(FULL, s0sum, 8 * qc);
            const float ib0 = 1.0f / __shfl_sync(FULL, s0sum, 8 * qc + 4);
            const float ia1 = 1.0f / __shfl_sync(FULL, s1sum, 8 * qc);
            const float ib1 = 1.0f / __shfl_sync(FULL, s1sum, 8 * qc + 4);
            if (s < S_TOTAL) {
                float* op = out + (size_t)s * 2048;
                {
                    const int ec = ebk + 2 * qc;
                    *reinterpret_cast<float2*>(&op[sq * 128 + ec]) =
                        make_float2((Oe[0][0] + Oo[0][0]) * ia0, (Oe[0][1] + Oo[0][1]) * ib0);
                    *reinterpret_cast<float2*>(&op[(sq + 8) * 128 + ec]) =
                        make_float2((Oe[0][2] + Oo[0][2]) * ia0, (Oe[0][3] + Oo[0][3]) * ib0);
                }
                {
                    const int ec = ebk + 8 + 2 * qc;
                    *reinterpret_cast<float2*>(&op[sq * 128 + ec]) =
                        make_float2((Oe[1][0] + Oo[1][0]) * ia1, (Oe[1][1] + Oo[1][1]) * ib1);
                    *reinterpret_cast<float2*>(&op[(sq + 8) * 128 + ec]) =
                        make_float2((Oe[1][2] + Oo[1][2]) * ia1, (Oe[1][3] + Oo[1][3]) * ib1);
                }
            }
        };
        fused(xbA, vbA, kaA, sA);
        fused(xbB, vbB, kaB, sB);

        asm volatile("bar.sync %0, 256;" :: "r"(barid) : "memory");   // (C)
        sbase += step; sA += step; sB += step;
    }
}

extern "C" void kernel_launch(void* const* d_in, const int* in_sizes, int n_in,
                              void* d_out, int out_size) {
    const float* x  = (const float*)d_in[0];
    const float* Wk = (const float*)d_in[1];
    const float* bk = (const float*)d_in[2];
    const float* Wv = (const float*)d_in[3];
    const float* bv = (const float*)d_in[4];
    float* out = (float*)d_out;

    int sms = 148;
    cudaDeviceGetAttribute(&sms, cudaDevAttrMultiProcessorCount, 0);
    if (sms <= 0) sms = 148;
    cudaFuncSetAttribute(nsa_mma, cudaFuncAttributeMaxDynamicSharedMemorySize, SMEM_BYTES);
    nsa_mma<<<sms, 512, SMEM_BYTES>>>(x, Wk, bk, Wv, bv, out);
}